// round 14
// baseline (speedup 1.0000x reference)
#include <cuda_runtime.h>
#include <cuda_bf16.h>
#include <cstdint>

#define BB 4
#define NN 4096
#define FF 32
#define KK 6
#define OO 128

// ---- GEMM tiling (R12 proven config: batch-serial, split-K=4) ----
#define BM 64                   // rows per CTA (4 warps x 16 rows)
#define KC 32                   // k per chunk
#define NSTAGE 4
#define KSPLIT 4
#define KRANGE (NN / KSPLIT)    // 1024
#define NCHUNK (KRANGE / KC)    // 32
#define PK (KK * FF)            // 192
#define NF (NN * FF)            // 131072

#define AROWF 40                                // A smem row stride in floats
#define AROWB (AROWF * 4)
#define A_BYTES (BM * AROWB)                    // 10240
#define BROWB 80                                // B smem row stride bytes
#define B_BYTES (FF * BROWB)                    // 2560
#define BHI_OFF A_BYTES
#define BLO_OFF (A_BYTES + B_BYTES)
#define STAGE_BYTES (A_BYTES + 2 * B_BYTES)     // 15360
#define SMEM_TOTAL (NSTAGE * STAGE_BYTES)       // 61440

// ---- scratch ----
__device__ float g_bufA[BB * NF];
__device__ float g_bufB[BB * NF];
__device__ float g_part[KSPLIT * NF];           // split-K partials, current batch (2 MB)
__device__ unsigned int g_cnt[NN / BM];         // per-row-tile arrival counters (zero-init)
__device__ __nv_bfloat16 g_btg_hi[2][BB * NF];  // T planes [b][f][n], ping-pong
__device__ __nv_bfloat16 g_btg_lo[2][BB * NF];
__device__ __nv_bfloat16 g_btp_hi[(size_t)BB * NN * PK];
__device__ __nv_bfloat16 g_btp_lo[(size_t)BB * NN * PK];
__device__ __nv_bfloat16 g_wt_hi[OO * PK];
__device__ __nv_bfloat16 g_wt_lo[OO * PK];

__device__ __forceinline__ uint32_t smem_u32(const void* p) {
    uint32_t a;
    asm("{ .reg .u64 t; cvta.to.shared.u64 t, %1; cvt.u32.u64 %0, t; }" : "=r"(a) : "l"(p));
    return a;
}
__device__ __forceinline__ void cp16(uint32_t dst, const void* src) {
    asm volatile("cp.async.cg.shared.global [%0], [%1], 16;" :: "r"(dst), "l"(src));
}
#define CP_COMMIT() asm volatile("cp.async.commit_group;" ::: "memory")
#define CP_WAIT(n)  asm volatile("cp.async.wait_group %0;" :: "n"(n) : "memory")

__device__ __forceinline__ void split2(float x, float y, uint32_t& hi, uint32_t& lo) {
    asm("cvt.rn.bf16x2.f32 %0, %1, %2;" : "=r"(hi) : "f"(y), "f"(x));
    const float h0 = __uint_as_float(hi << 16);
    const float h1 = __uint_as_float(hi & 0xFFFF0000u);
    const float l0 = x - h0;
    const float l1 = y - h1;
    asm("cvt.rn.bf16x2.f32 %0, %1, %2;" : "=r"(lo) : "f"(l1), "f"(l0));
}

__device__ __forceinline__ void mma16816(float* c,
                                         uint32_t a0, uint32_t a1, uint32_t a2, uint32_t a3,
                                         uint32_t b0, uint32_t b1) {
    asm volatile(
        "mma.sync.aligned.m16n8k16.row.col.f32.bf16.bf16.f32 "
        "{%0,%1,%2,%3}, {%4,%5,%6,%7}, {%8,%9}, {%0,%1,%2,%3};"
        : "+f"(c[0]), "+f"(c[1]), "+f"(c[2]), "+f"(c[3])
        : "r"(a0), "r"(a1), "r"(a2), "r"(a3), "r"(b0), "r"(b1));
}

// ---------------------------------------------------------------------------
// Prep x: fp32 [b][n][f] -> planes[0] ([b][f][n] hi/lo)  +  btp slot 0
// ---------------------------------------------------------------------------
__global__ __launch_bounds__(256) void prep_b(
    const float* __restrict__ T,
    __nv_bfloat16* __restrict__ gHi,
    __nv_bfloat16* __restrict__ gLo,
    __nv_bfloat16* __restrict__ pHi,
    __nv_bfloat16* __restrict__ pLo)
{
    const int idx = blockIdx.x * 256 + threadIdx.x;
    const int n = idx & (NN - 1);
    const int f = (idx >> 12) & (FF - 1);
    const int b = idx >> 17;
    const float a = T[((size_t)b * NN + n) * FF + f];
    const __nv_bfloat16 h = __float2bfloat16_rn(a);
    const __nv_bfloat16 l = __float2bfloat16_rn(a - __bfloat162float(h));
    gHi[idx] = h;
    gLo[idx] = l;
    const size_t pidx = ((size_t)b * NN + n) * PK + f;
    pHi[pidx] = h;
    pLo[pidx] = l;
}

// ---------------------------------------------------------------------------
// Prep W': Wt[o][k6*32+f] = theta[k6] * W[k6][f][o], bf16 hi/lo
// ---------------------------------------------------------------------------
__global__ __launch_bounds__(256) void prep_w(
    const float* __restrict__ W,
    const float* __restrict__ theta,
    __nv_bfloat16* __restrict__ wHi,
    __nv_bfloat16* __restrict__ wLo)
{
    const int idx = blockIdx.x * 256 + threadIdx.x;
    const int o  = idx & (OO - 1);
    const int kf = idx >> 7;
    const int k6 = kf >> 5;
    const float v = theta[k6] * W[(size_t)kf * OO + o];
    const __nv_bfloat16 h = __float2bfloat16_rn(v);
    const size_t w = (size_t)o * PK + kf;
    wHi[w] = h;
    wLo[w] = __float2bfloat16_rn(v - __bfloat162float(h));
}

// ---------------------------------------------------------------------------
// Split-K HMMA GEMM + fused last-CTA finalize.
// Each (row-tile, ks) CTA: R12 mainloop -> raw partial -> arrival counter.
// Last arriver per row-tile: sums 4 partials, applies alpha/beta, writes
// Tnew fp32 + btg bf16 planes + btp proj slab; resets counter.
// ---------------------------------------------------------------------------
__global__ __launch_bounds__(128, 3) void cheb_gemm_fused(
    const float* __restrict__ Lmat,
    const __nv_bfloat16* __restrict__ BtHi,
    const __nv_bfloat16* __restrict__ BtLo,
    const float* __restrict__ Tpp,
    float* __restrict__ Tnew,
    float alpha, float beta,
    __nv_bfloat16* __restrict__ outGHi,
    __nv_bfloat16* __restrict__ outGLo,
    __nv_bfloat16* __restrict__ outPHi,
    __nv_bfloat16* __restrict__ outPLo,
    int b, int pslot)
{
    extern __shared__ __align__(16) char smem[];
    const uint32_t sb = smem_u32(smem);

    const int tid  = threadIdx.x;
    const int lane = tid & 31;
    const int wl   = tid >> 5;       // warp 0..3, owns rows wl*16..+15
    const int ks   = blockIdx.y;
    const int row0 = blockIdx.x * BM;
    const int kbase = ks * KRANGE;

    const float* Lb = Lmat + ((size_t)b * NN + row0) * NN;
    const __nv_bfloat16* bhsrc = BtHi + (size_t)b * FF * NN;
    const __nv_bfloat16* blsrc = BtLo + (size_t)b * FF * NN;

    auto issue = [&](int c) {
        const uint32_t st = sb + (uint32_t)(c % NSTAGE) * STAGE_BYTES;
        const int k0 = kbase + c * KC;
#pragma unroll
        for (int i = 0; i < 4; i++) {
            const int idx = i * 128 + tid;
            const int r = idx >> 3, g = idx & 7;
            cp16(st + r * AROWB + g * 16, Lb + (size_t)r * NN + k0 + g * 4);
        }
        const int f = tid >> 2, g = tid & 3;
        cp16(st + BHI_OFF + f * BROWB + g * 16, bhsrc + (size_t)f * NN + k0 + g * 8);
        cp16(st + BLO_OFF + f * BROWB + g * 16, blsrc + (size_t)f * NN + k0 + g * 8);
    };

#pragma unroll
    for (int s = 0; s < NSTAGE - 1; s++) { issue(s); CP_COMMIT(); }

    float acc[4][4];
#pragma unroll
    for (int i = 0; i < 4; i++)
#pragma unroll
        for (int j = 0; j < 4; j++) acc[i][j] = 0.0f;

    const int rsub = (lane >> 2);
    const int kq   = (lane & 3) * 2;

    for (int i = 0; i < NCHUNK; i++) {
        CP_WAIT(NSTAGE - 2);
        __syncthreads();
        if (i + NSTAGE - 1 < NCHUNK) issue(i + NSTAGE - 1);
        CP_COMMIT();

        const char* st = smem + (i % NSTAGE) * STAGE_BYTES;
        const float* As = (const float*)st;

#pragma unroll
        for (int kf = 0; kf < 2; kf++) {
            const int kb = kf * 16;
            const float* Ap = As + (wl * 16 + rsub) * AROWF + kb + kq;
            const float2 p0 = *(const float2*)(Ap);
            const float2 p1 = *(const float2*)(Ap + 8 * AROWF);
            const float2 p2 = *(const float2*)(Ap + 8);
            const float2 p3 = *(const float2*)(Ap + 8 * AROWF + 8);

            uint32_t ah0, ah1, ah2, ah3, al0, al1, al2, al3;
            split2(p0.x, p0.y, ah0, al0);
            split2(p1.x, p1.y, ah1, al1);
            split2(p2.x, p2.y, ah2, al2);
            split2(p3.x, p3.y, ah3, al3);

#pragma unroll
            for (int nb = 0; nb < 4; nb++) {
                const int n = nb * 8 + rsub;
                const char* bp = st + BHI_OFF + n * BROWB + (kb + kq) * 2;
                const uint32_t bh0 = *(const uint32_t*)(bp);
                const uint32_t bh1 = *(const uint32_t*)(bp + 16);
                const uint32_t bl0 = *(const uint32_t*)(bp + (BLO_OFF - BHI_OFF));
                const uint32_t bl1 = *(const uint32_t*)(bp + (BLO_OFF - BHI_OFF) + 16);

                mma16816(acc[nb], ah0, ah1, ah2, ah3, bh0, bh1);
                mma16816(acc[nb], ah0, ah1, ah2, ah3, bl0, bl1);
                mma16816(acc[nb], al0, al1, al2, al3, bh0, bh1);
            }
        }
    }

    // ---- write raw partial for this k-quarter ----
    const int rl = row0 + wl * 16 + rsub;         // row within batch (0..4095)
    float* pk = g_part + (size_t)ks * NF;
#pragma unroll
    for (int nb = 0; nb < 4; nb++) {
        const int col = nb * 8 + kq;
        const size_t l0 = (size_t)rl * FF + col;
        *(float2*)(pk + l0)          = make_float2(acc[nb][0], acc[nb][1]);
        *(float2*)(pk + l0 + 8 * FF) = make_float2(acc[nb][2], acc[nb][3]);
    }
    __threadfence();                              // release partial stores

    __shared__ unsigned int s_old;
    __syncthreads();
    if (tid == 0) s_old = atomicAdd(&g_cnt[blockIdx.x], 1u);
    __syncthreads();
    if (s_old != KSPLIT - 1) return;              // uniform across CTA (shared)

    // ---- last arriver: finalize this row tile ----
    __threadfence();                              // acquire others' partials

    const float* q0 = g_part;
    const float* q1 = g_part + NF;
    const float* q2 = g_part + 2 * (size_t)NF;
    const float* q3 = g_part + 3 * (size_t)NF;

#pragma unroll
    for (int nb = 0; nb < 4; nb++) {
        const int col = nb * 8 + kq;
        const size_t l0 = (size_t)rl * FF + col;
        const size_t l1 = l0 + 8 * FF;
        const float2 a0 = *(const float2*)(q0 + l0), b0f = *(const float2*)(q1 + l0);
        const float2 c0 = *(const float2*)(q2 + l0), d0 = *(const float2*)(q3 + l0);
        const float2 a1 = *(const float2*)(q0 + l1), b1f = *(const float2*)(q1 + l1);
        const float2 c1 = *(const float2*)(q2 + l1), d1 = *(const float2*)(q3 + l1);

        const size_t o0 = ((size_t)b * NN + rl) * FF + col;
        const size_t o1 = o0 + 8 * FF;
        float2 v0, v1;
        v0.x = alpha * (a0.x + b0f.x + c0.x + d0.x);
        v0.y = alpha * (a0.y + b0f.y + c0.y + d0.y);
        v1.x = alpha * (a1.x + b1f.x + c1.x + d1.x);
        v1.y = alpha * (a1.y + b1f.y + c1.y + d1.y);
        if (beta != 0.0f) {
            const float2 t0 = *(const float2*)(Tpp + o0);
            const float2 t1 = *(const float2*)(Tpp + o1);
            v0.x += beta * t0.x; v0.y += beta * t0.y;
            v1.x += beta * t1.x; v1.y += beta * t1.y;
        }
        *(float2*)(Tnew + o0) = v0;
        *(float2*)(Tnew + o1) = v1;

        uint32_t h0, l0b, h1, l1b;
        split2(v0.x, v0.y, h0, l0b);
        split2(v1.x, v1.y, h1, l1b);

        const size_t p0 = ((size_t)b * NN + rl) * PK + pslot * FF + col;
        const size_t p1 = p0 + 8 * PK;
        *(uint32_t*)(outPHi + p0) = h0;
        *(uint32_t*)(outPLo + p0) = l0b;
        *(uint32_t*)(outPHi + p1) = h1;
        *(uint32_t*)(outPLo + p1) = l1b;

        const size_t gA = ((size_t)b * FF + col) * NN;
        ((uint16_t*)outGHi)[gA + rl]           = (uint16_t)(h0 & 0xFFFF);
        ((uint16_t*)outGHi)[gA + NN + rl]      = (uint16_t)(h0 >> 16);
        ((uint16_t*)outGLo)[gA + rl]           = (uint16_t)(l0b & 0xFFFF);
        ((uint16_t*)outGLo)[gA + NN + rl]      = (uint16_t)(l0b >> 16);
        ((uint16_t*)outGHi)[gA + rl + 8]       = (uint16_t)(h1 & 0xFFFF);
        ((uint16_t*)outGHi)[gA + NN + rl + 8]  = (uint16_t)(h1 >> 16);
        ((uint16_t*)outGLo)[gA + rl + 8]       = (uint16_t)(l1b & 0xFFFF);
        ((uint16_t*)outGLo)[gA + NN + rl + 8]  = (uint16_t)(l1b >> 16);
    }

    __syncthreads();
    if (tid == 0) g_cnt[blockIdx.x] = 0;          // reset for next launch / replay
}

// ---------------------------------------------------------------------------
// Fused projection: out[16384,128] = A[16384,192] @ W'[192,128]
// ---------------------------------------------------------------------------
#define PJ_STRIDE 100
#define PJ_SMEM (4 * 64 * PJ_STRIDE * 4)

__global__ __launch_bounds__(256, 2) void proj_mma(
    const __nv_bfloat16* __restrict__ pHi,
    const __nv_bfloat16* __restrict__ pLo,
    const __nv_bfloat16* __restrict__ wHi,
    const __nv_bfloat16* __restrict__ wLo,
    float* __restrict__ out)
{
    extern __shared__ __align__(16) char smem[];
    uint32_t* Ah = (uint32_t*)smem;
    uint32_t* Al = Ah + 64 * PJ_STRIDE;
    uint32_t* Bh = Al + 64 * PJ_STRIDE;
    uint32_t* Bl = Bh + 64 * PJ_STRIDE;
    const uint32_t sAh = smem_u32(Ah), sAl = smem_u32(Al);
    const uint32_t sBh = smem_u32(Bh), sBl = smem_u32(Bl);

    const int tid = threadIdx.x;
    const int r0 = blockIdx.x * 64;
    const int oh = blockIdx.y;

#pragma unroll
    for (int i = 0; i < 6; i++) {
        const int idx = i * 256 + tid;
        const int row = idx / 24;
        const int ch  = idx % 24;
        cp16(sAh + row * 400 + ch * 16, pHi + (size_t)(r0 + row) * PK + ch * 8);
        cp16(sAl + row * 400 + ch * 16, pLo + (size_t)(r0 + row) * PK + ch * 8);
        cp16(sBh + row * 400 + ch * 16, wHi + (size_t)(oh * 64 + row) * PK + ch * 8);
        cp16(sBl + row * 400 + ch * 16, wLo + (size_t)(oh * 64 + row) * PK + ch * 8);
    }
    CP_COMMIT();
    CP_WAIT(0);
    __syncthreads();

    const int lane = tid & 31;
    const int wid  = tid >> 5;
    const int mw   = wid & 3;
    const int ow   = wid >> 2;
    const int rsub = lane >> 2;
    const int q    = lane & 3;

    float acc[4][4];
#pragma unroll
    for (int i = 0; i < 4; i++)
#pragma unroll
        for (int j = 0; j < 4; j++) acc[i][j] = 0.0f;

#pragma unroll
    for (int ki = 0; ki < 12; ki++) {
        const int kb2 = ki * 8;
        const uint32_t* Ar = Ah + (mw * 16 + rsub) * PJ_STRIDE + kb2 + q;
        const uint32_t* Alr = Al + (mw * 16 + rsub) * PJ_STRIDE + kb2 + q;
        const uint32_t ah0 = Ar[0],  ah1 = Ar[8 * PJ_STRIDE],  ah2 = Ar[4],  ah3 = Ar[8 * PJ_STRIDE + 4];
        const uint32_t al0 = Alr[0], al1 = Alr[8 * PJ_STRIDE], al2 = Alr[4], al3 = Alr[8 * PJ_STRIDE + 4];

#pragma unroll
        for (int nb = 0; nb < 4; nb++) {
            const int ob = ow * 32 + nb * 8 + rsub;
            const uint32_t* Br = Bh + ob * PJ_STRIDE + kb2 + q;
            const uint32_t* Blr = Bl + ob * PJ_STRIDE + kb2 + q;
            const uint32_t bh0 = Br[0], bh1 = Br[4];
            const uint32_t bl0 = Blr[0], bl1 = Blr[4];

            mma16816(acc[nb], ah0, ah1, ah2, ah3, bh0, bh1);
            mma16816(acc[nb], ah0, ah1, ah2, ah3, bl0, bl1);
            mma16816(acc[nb], al0, al1, al2, al3, bh0, bh1);
        }
    }

    const int row = r0 + mw * 16 + rsub;
#pragma unroll
    for (int nb = 0; nb < 4; nb++) {
        const int col = oh * 64 + ow * 32 + nb * 8 + q * 2;
        *(float2*)(out + (size_t)row * OO + col)       = make_float2(acc[nb][0], acc[nb][1]);
        *(float2*)(out + (size_t)(row + 8) * OO + col) = make_float2(acc[nb][2], acc[nb][3]);
    }
}

// ---------------------------------------------------------------------------
// Launcher: batch-serial (L2-resident L), split-K GEMM with fused finalize
// ---------------------------------------------------------------------------
extern "C" void kernel_launch(void* const* d_in, const int* in_sizes, int n_in,
                              void* d_out, int out_size)
{
    const float* x = nullptr;
    const float* Lm = nullptr;
    const float* W = nullptr;
    const float* theta = nullptr;
    for (int i = 0; i < n_in; i++) {
        switch (in_sizes[i]) {
            case BB * NN * FF: x = (const float*)d_in[i]; break;
            case BB * NN * NN: Lm = (const float*)d_in[i]; break;
            case KK * FF * OO: W = (const float*)d_in[i]; break;
            case KK:           theta = (const float*)d_in[i]; break;
            default: break;
        }
    }
    float* out = (float*)d_out;

    float *bufA = nullptr, *bufB = nullptr;
    __nv_bfloat16 *btgHi = nullptr, *btgLo = nullptr;
    __nv_bfloat16 *btpHi = nullptr, *btpLo = nullptr;
    __nv_bfloat16 *wtHi = nullptr, *wtLo = nullptr;
    cudaGetSymbolAddress((void**)&bufA, g_bufA);
    cudaGetSymbolAddress((void**)&bufB, g_bufB);
    cudaGetSymbolAddress((void**)&btgHi, g_btg_hi);
    cudaGetSymbolAddress((void**)&btgLo, g_btg_lo);
    cudaGetSymbolAddress((void**)&btpHi, g_btp_hi);
    cudaGetSymbolAddress((void**)&btpLo, g_btp_lo);
    cudaGetSymbolAddress((void**)&wtHi, g_wt_hi);
    cudaGetSymbolAddress((void**)&wtLo, g_wt_lo);

    __nv_bfloat16* gHi[2] = { btgHi, btgHi + (size_t)BB * NF };
    __nv_bfloat16* gLo[2] = { btgLo, btgLo + (size_t)BB * NF };

    cudaFuncSetAttribute(cheb_gemm_fused, cudaFuncAttributeMaxDynamicSharedMemorySize, SMEM_TOTAL);
    cudaFuncSetAttribute(proj_mma, cudaFuncAttributeMaxDynamicSharedMemorySize, PJ_SMEM);

    const dim3 gGrid(NN / BM, KSPLIT);      // (64, 4) = 256 CTAs per batch-step
    const dim3 bGrid((BB * FF * NN) / 256);
    const dim3 wGrid((PK * OO) / 256);
    const dim3 pjGrid((BB * NN) / 64, 2);

    prep_w<<<wGrid, 256>>>(W, theta, wtHi, wtLo);
    prep_b<<<bGrid, 256>>>(x, gHi[0], gLo[0], btpHi, btpLo);

    // step tables
    const float* TppTab[6]   = { nullptr, x,    x,    bufA, bufB, bufA };
    float*       TnewTab[6]  = { nullptr, bufA, bufB, bufA, bufB, bufA };
    const float  alphaTab[6] = { 0, 1.0f, 2.0f, 2.0f, 2.0f, 2.0f };
    const float  betaTab[6]  = { 0, 0.0f, -1.0f, -1.0f, -1.0f, -1.0f };

    for (int b = 0; b < BB; b++) {
        for (int k = 1; k <= 5; k++) {
            const int rdPlane = (k - 1) & 1;   // step1 reads plane0 (x)
            const int wrPlane = k & 1;
            cheb_gemm_fused<<<gGrid, 128, SMEM_TOTAL>>>(
                Lm, gHi[rdPlane], gLo[rdPlane],
                TppTab[k], TnewTab[k], alphaTab[k], betaTab[k],
                gHi[wrPlane], gLo[wrPlane], btpHi, btpLo, b, k);
        }
    }

    // out = sum_k theta_k T_k W_k
    proj_mma<<<pjGrid, 256, PJ_SMEM>>>(btpHi, btpLo, wtHi, wtLo, out);
}

// round 15
// speedup vs baseline: 1.7267x; 1.7267x over previous
#include <cuda_runtime.h>
#include <cuda_bf16.h>
#include <cstdint>

#define BB 4
#define NN 4096
#define FF 32
#define KK 6
#define OO 128

// ---- GEMM tiling (R4 proven config) ----
#define BM 64                   // rows per CTA (4 warps x 16 rows)
#define KC 32                   // k per chunk
#define NSTAGE 4
#define NCHUNK (NN / KC)        // 128
#define PK (KK * FF)            // 192

#define AROWF 40                                // A smem row stride in floats
#define AROWB (AROWF * 4)
#define A_BYTES (BM * AROWB)                    // 10240
#define BROWB 80                                // B smem row stride bytes
#define B_BYTES (FF * BROWB)                    // 2560
#define BHI_OFF A_BYTES
#define BLO_OFF (A_BYTES + B_BYTES)
#define STAGE_BYTES (A_BYTES + 2 * B_BYTES)     // 15360
#define SMEM_TOTAL (NSTAGE * STAGE_BYTES)       // 61440

// ---- scratch ----
__device__ float g_bufA[BB * NN * FF];
__device__ float g_bufB[BB * NN * FF];
__device__ __nv_bfloat16 g_btg_hi[2][BB * FF * NN];
__device__ __nv_bfloat16 g_btg_lo[2][BB * FF * NN];
__device__ __nv_bfloat16 g_btp_hi[(size_t)BB * NN * PK];
__device__ __nv_bfloat16 g_btp_lo[(size_t)BB * NN * PK];
__device__ __nv_bfloat16 g_wt_hi[OO * PK];
__device__ __nv_bfloat16 g_wt_lo[OO * PK];

__device__ __forceinline__ uint32_t smem_u32(const void* p) {
    uint32_t a;
    asm("{ .reg .u64 t; cvta.to.shared.u64 t, %1; cvt.u32.u64 %0, t; }" : "=r"(a) : "l"(p));
    return a;
}
__device__ __forceinline__ void cp16(uint32_t dst, const void* src) {
    asm volatile("cp.async.cg.shared.global [%0], [%1], 16;" :: "r"(dst), "l"(src));
}
#define CP_COMMIT() asm volatile("cp.async.commit_group;" ::: "memory")
#define CP_WAIT(n)  asm volatile("cp.async.wait_group %0;" :: "n"(n) : "memory")

__device__ __forceinline__ void split2(float x, float y, uint32_t& hi, uint32_t& lo) {
    asm("cvt.rn.bf16x2.f32 %0, %1, %2;" : "=r"(hi) : "f"(y), "f"(x));
    const float h0 = __uint_as_float(hi << 16);
    const float h1 = __uint_as_float(hi & 0xFFFF0000u);
    const float l0 = x - h0;
    const float l1 = y - h1;
    asm("cvt.rn.bf16x2.f32 %0, %1, %2;" : "=r"(lo) : "f"(l1), "f"(l0));
}

__device__ __forceinline__ void mma16816(float* c,
                                         uint32_t a0, uint32_t a1, uint32_t a2, uint32_t a3,
                                         uint32_t b0, uint32_t b1) {
    asm volatile(
        "mma.sync.aligned.m16n8k16.row.col.f32.bf16.bf16.f32 "
        "{%0,%1,%2,%3}, {%4,%5,%6,%7}, {%8,%9}, {%0,%1,%2,%3};"
        : "+f"(c[0]), "+f"(c[1]), "+f"(c[2]), "+f"(c[3])
        : "r"(a0), "r"(a1), "r"(a2), "r"(a3), "r"(b0), "r"(b1));
}

// ---------------------------------------------------------------------------
// Prep x: fp32 [b][n][f] -> btg ([b][f][n] hi/lo)  +  btp slot 0
// ---------------------------------------------------------------------------
__global__ __launch_bounds__(256) void prep_b(
    const float* __restrict__ T,
    __nv_bfloat16* __restrict__ gHi,
    __nv_bfloat16* __restrict__ gLo,
    __nv_bfloat16* __restrict__ pHi,
    __nv_bfloat16* __restrict__ pLo)
{
    const int idx = blockIdx.x * 256 + threadIdx.x;
    const int n = idx & (NN - 1);
    const int f = (idx >> 12) & (FF - 1);
    const int b = idx >> 17;
    const float a = T[((size_t)b * NN + n) * FF + f];
    const __nv_bfloat16 h = __float2bfloat16_rn(a);
    const __nv_bfloat16 l = __float2bfloat16_rn(a - __bfloat162float(h));
    gHi[idx] = h;
    gLo[idx] = l;
    const size_t pidx = ((size_t)b * NN + n) * PK + f;
    pHi[pidx] = h;
    pLo[pidx] = l;
}

// ---------------------------------------------------------------------------
// Prep W': Wt[o][k6*32+f] = theta[k6] * W[k6][f][o], bf16 hi/lo
// ---------------------------------------------------------------------------
__global__ __launch_bounds__(256) void prep_w(
    const float* __restrict__ W,
    const float* __restrict__ theta,
    __nv_bfloat16* __restrict__ wHi,
    __nv_bfloat16* __restrict__ wLo)
{
    const int idx = blockIdx.x * 256 + threadIdx.x;
    const int o  = idx & (OO - 1);
    const int kf = idx >> 7;
    const int k6 = kf >> 5;
    const float v = theta[k6] * W[(size_t)kf * OO + o];
    const __nv_bfloat16 h = __float2bfloat16_rn(v);
    const size_t w = (size_t)o * PK + kf;
    wHi[w] = h;
    wLo[w] = __float2bfloat16_rn(v - __bfloat162float(h));
}

// ---------------------------------------------------------------------------
// HMMA GEMM (R4 config), interleaved cp.async issue, UNCONDITIONAL commit
// per iteration (tail accounting: empty groups keep CP_WAIT(N-2) aligned).
// Tnew = alpha * L @ Tprev + beta * Tpp, plus bf16 term export.
// ---------------------------------------------------------------------------
__global__ __launch_bounds__(128, 3) void cheb_gemm_tc(
    const float* __restrict__ Lmat,
    const __nv_bfloat16* __restrict__ BtHi,
    const __nv_bfloat16* __restrict__ BtLo,
    const float* __restrict__ Tpp,
    float* __restrict__ Tnew,
    float alpha, float beta,
    __nv_bfloat16* __restrict__ outGHi,
    __nv_bfloat16* __restrict__ outGLo,
    __nv_bfloat16* __restrict__ outPHi,
    __nv_bfloat16* __restrict__ outPLo,
    int pslot)
{
    extern __shared__ __align__(16) char smem[];
    const uint32_t sb = smem_u32(smem);

    const int tid  = threadIdx.x;
    const int lane = tid & 31;
    const int wl   = tid >> 5;
    const int b    = blockIdx.y;
    const int row0 = blockIdx.x * BM;

    const float* Lb = Lmat + ((size_t)b * NN + row0) * NN;
    const __nv_bfloat16* bhsrc = BtHi + (size_t)b * FF * NN;
    const __nv_bfloat16* blsrc = BtLo + (size_t)b * FF * NN;

    // A loads, two cp16 per call (half = 0 or 1)
    auto issueA = [&](int c, int half) {
        const uint32_t st = sb + (uint32_t)(c % NSTAGE) * STAGE_BYTES;
        const int k0 = c * KC;
#pragma unroll
        for (int i = 0; i < 2; i++) {
            const int idx = (half * 2 + i) * 128 + tid;
            const int r = idx >> 3, g = idx & 7;
            cp16(st + r * AROWB + g * 16, Lb + (size_t)r * NN + k0 + g * 4);
        }
    };
    // B loads, two cp16 per thread
    auto issueB = [&](int c) {
        const uint32_t st = sb + (uint32_t)(c % NSTAGE) * STAGE_BYTES;
        const int k0 = c * KC;
        const int f = tid >> 2, g = tid & 3;
        cp16(st + BHI_OFF + f * BROWB + g * 16, bhsrc + (size_t)f * NN + k0 + g * 8);
        cp16(st + BLO_OFF + f * BROWB + g * 16, blsrc + (size_t)f * NN + k0 + g * 8);
    };

    // prologue: stages 0..2
#pragma unroll
    for (int s = 0; s < NSTAGE - 1; s++) {
        issueA(s, 0); issueA(s, 1); issueB(s);
        CP_COMMIT();
    }

    float acc[4][4];
#pragma unroll
    for (int i = 0; i < 4; i++)
#pragma unroll
        for (int j = 0; j < 4; j++) acc[i][j] = 0.0f;

    const int rsub = (lane >> 2);
    const int kq   = (lane & 3) * 2;

    for (int i = 0; i < NCHUNK; i++) {
        CP_WAIT(NSTAGE - 2);
        __syncthreads();

        const bool pf = (i + NSTAGE - 1 < NCHUNK);
        const int  pc = i + NSTAGE - 1;
        const char* st = smem + (i % NSTAGE) * STAGE_BYTES;
        const float* As = (const float*)st;

#pragma unroll
        for (int kf = 0; kf < 2; kf++) {
            const int kb = kf * 16;
            const float* Ap = As + (wl * 16 + rsub) * AROWF + kb + kq;
            const float2 p0 = *(const float2*)(Ap);
            const float2 p1 = *(const float2*)(Ap + 8 * AROWF);
            const float2 p2 = *(const float2*)(Ap + 8);
            const float2 p3 = *(const float2*)(Ap + 8 * AROWF + 8);

            uint32_t ah0, ah1, ah2, ah3, al0, al1, al2, al3;
            split2(p0.x, p0.y, ah0, al0);
            split2(p1.x, p1.y, ah1, al1);
            split2(p2.x, p2.y, ah2, al2);
            split2(p3.x, p3.y, ah3, al3);

#pragma unroll
            for (int nb = 0; nb < 4; nb++) {
                const int n = nb * 8 + rsub;
                const char* bp = st + BHI_OFF + n * BROWB + (kb + kq) * 2;
                const uint32_t bh0 = *(const uint32_t*)(bp);
                const uint32_t bh1 = *(const uint32_t*)(bp + 16);
                const uint32_t bl0 = *(const uint32_t*)(bp + (BLO_OFF - BHI_OFF));
                const uint32_t bl1 = *(const uint32_t*)(bp + (BLO_OFF - BHI_OFF) + 16);

                mma16816(acc[nb], ah0, ah1, ah2, ah3, bh0, bh1);
                mma16816(acc[nb], ah0, ah1, ah2, ah3, bl0, bl1);
                mma16816(acc[nb], al0, al1, al2, al3, bh0, bh1);
            }

            // interleaved prefetch slices (low-burst issue)
            if (pf) {
                if (kf == 0) {
                    issueA(pc, 0);
                } else {
                    issueA(pc, 1);
                    issueB(pc);
                }
            }
        }
        CP_COMMIT();   // UNCONDITIONAL: empty tail groups keep wait-count aligned
    }

    // ---- epilogue: Tnew fp32 + btg [f][n] hi/lo + btp slab slot ----
    const int rA = row0 + wl * 16 + rsub;
#pragma unroll
    for (int nb = 0; nb < 4; nb++) {
        const int col = nb * 8 + kq;
        const size_t o0 = ((size_t)b * NN + rA) * FF + col;
        const size_t o1 = o0 + 8 * FF;
        float2 v0 = make_float2(alpha * acc[nb][0], alpha * acc[nb][1]);
        float2 v1 = make_float2(alpha * acc[nb][2], alpha * acc[nb][3]);
        if (beta != 0.0f) {
            const float2 q0 = *(const float2*)(Tpp + o0);
            const float2 q1 = *(const float2*)(Tpp + o1);
            v0.x += beta * q0.x; v0.y += beta * q0.y;
            v1.x += beta * q1.x; v1.y += beta * q1.y;
        }
        *(float2*)(Tnew + o0) = v0;
        *(float2*)(Tnew + o1) = v1;

        uint32_t h0, l0, h1, l1;
        split2(v0.x, v0.y, h0, l0);
        split2(v1.x, v1.y, h1, l1);

        const size_t p0 = ((size_t)b * NN + rA) * PK + pslot * FF + col;
        const size_t p1 = p0 + 8 * PK;
        *(uint32_t*)(outPHi + p0) = h0;
        *(uint32_t*)(outPLo + p0) = l0;
        *(uint32_t*)(outPHi + p1) = h1;
        *(uint32_t*)(outPLo + p1) = l1;

        const size_t gA = ((size_t)b * FF + col) * NN;
        ((uint16_t*)outGHi)[gA + rA]           = (uint16_t)(h0 & 0xFFFF);
        ((uint16_t*)outGHi)[gA + NN + rA]      = (uint16_t)(h0 >> 16);
        ((uint16_t*)outGLo)[gA + rA]           = (uint16_t)(l0 & 0xFFFF);
        ((uint16_t*)outGLo)[gA + NN + rA]      = (uint16_t)(l0 >> 16);
        ((uint16_t*)outGHi)[gA + rA + 8]       = (uint16_t)(h1 & 0xFFFF);
        ((uint16_t*)outGHi)[gA + NN + rA + 8]  = (uint16_t)(h1 >> 16);
        ((uint16_t*)outGLo)[gA + rA + 8]       = (uint16_t)(l1 & 0xFFFF);
        ((uint16_t*)outGLo)[gA + NN + rA + 8]  = (uint16_t)(l1 >> 16);
    }
}

// ---------------------------------------------------------------------------
// Fused projection: out[16384,128] = A[16384,192] @ W'[192,128]
// ---------------------------------------------------------------------------
#define PJ_STRIDE 100
#define PJ_SMEM (4 * 64 * PJ_STRIDE * 4)

__global__ __launch_bounds__(256, 2) void proj_mma(
    const __nv_bfloat16* __restrict__ pHi,
    const __nv_bfloat16* __restrict__ pLo,
    const __nv_bfloat16* __restrict__ wHi,
    const __nv_bfloat16* __restrict__ wLo,
    float* __restrict__ out)
{
    extern __shared__ __align__(16) char smem[];
    uint32_t* Ah = (uint32_t*)smem;
    uint32_t* Al = Ah + 64 * PJ_STRIDE;
    uint32_t* Bh = Al + 64 * PJ_STRIDE;
    uint32_t* Bl = Bh + 64 * PJ_STRIDE;
    const uint32_t sAh = smem_u32(Ah), sAl = smem_u32(Al);
    const uint32_t sBh = smem_u32(Bh), sBl = smem_u32(Bl);

    const int tid = threadIdx.x;
    const int r0 = blockIdx.x * 64;
    const int oh = blockIdx.y;

#pragma unroll
    for (int i = 0; i < 6; i++) {
        const int idx = i * 256 + tid;
        const int row = idx / 24;
        const int ch  = idx % 24;
        cp16(sAh + row * 400 + ch * 16, pHi + (size_t)(r0 + row) * PK + ch * 8);
        cp16(sAl + row * 400 + ch * 16, pLo + (size_t)(r0 + row) * PK + ch * 8);
        cp16(sBh + row * 400 + ch * 16, wHi + (size_t)(oh * 64 + row) * PK + ch * 8);
        cp16(sBl + row * 400 + ch * 16, wLo + (size_t)(oh * 64 + row) * PK + ch * 8);
    }
    CP_COMMIT();
    CP_WAIT(0);
    __syncthreads();

    const int lane = tid & 31;
    const int wid  = tid >> 5;
    const int mw   = wid & 3;
    const int ow   = wid >> 2;
    const int rsub = lane >> 2;
    const int q    = lane & 3;

    float acc[4][4];
#pragma unroll
    for (int i = 0; i < 4; i++)
#pragma unroll
        for (int j = 0; j < 4; j++) acc[i][j] = 0.0f;

#pragma unroll
    for (int ki = 0; ki < 12; ki++) {
        const int kb2 = ki * 8;
        const uint32_t* Ar = Ah + (mw * 16 + rsub) * PJ_STRIDE + kb2 + q;
        const uint32_t* Alr = Al + (mw * 16 + rsub) * PJ_STRIDE + kb2 + q;
        const uint32_t ah0 = Ar[0],  ah1 = Ar[8 * PJ_STRIDE],  ah2 = Ar[4],  ah3 = Ar[8 * PJ_STRIDE + 4];
        const uint32_t al0 = Alr[0], al1 = Alr[8 * PJ_STRIDE], al2 = Alr[4], al3 = Alr[8 * PJ_STRIDE + 4];

#pragma unroll
        for (int nb = 0; nb < 4; nb++) {
            const int ob = ow * 32 + nb * 8 + rsub;
            const uint32_t* Br = Bh + ob * PJ_STRIDE + kb2 + q;
            const uint32_t* Blr = Bl + ob * PJ_STRIDE + kb2 + q;
            const uint32_t bh0 = Br[0], bh1 = Br[4];
            const uint32_t bl0 = Blr[0], bl1 = Blr[4];

            mma16816(acc[nb], ah0, ah1, ah2, ah3, bh0, bh1);
            mma16816(acc[nb], ah0, ah1, ah2, ah3, bl0, bl1);
            mma16816(acc[nb], al0, al1, al2, al3, bh0, bh1);
        }
    }

    const int row = r0 + mw * 16 + rsub;
#pragma unroll
    for (int nb = 0; nb < 4; nb++) {
        const int col = oh * 64 + ow * 32 + nb * 8 + q * 2;
        *(float2*)(out + (size_t)row * OO + col)       = make_float2(acc[nb][0], acc[nb][1]);
        *(float2*)(out + (size_t)(row + 8) * OO + col) = make_float2(acc[nb][2], acc[nb][3]);
    }
}

// ---------------------------------------------------------------------------
// Launcher
// ---------------------------------------------------------------------------
extern "C" void kernel_launch(void* const* d_in, const int* in_sizes, int n_in,
                              void* d_out, int out_size)
{
    const float* x = nullptr;
    const float* Lm = nullptr;
    const float* W = nullptr;
    const float* theta = nullptr;
    for (int i = 0; i < n_in; i++) {
        switch (in_sizes[i]) {
            case BB * NN * FF: x = (const float*)d_in[i]; break;
            case BB * NN * NN: Lm = (const float*)d_in[i]; break;
            case KK * FF * OO: W = (const float*)d_in[i]; break;
            case KK:           theta = (const float*)d_in[i]; break;
            default: break;
        }
    }
    float* out = (float*)d_out;

    float *bufA = nullptr, *bufB = nullptr;
    __nv_bfloat16 *btgHi = nullptr, *btgLo = nullptr;
    __nv_bfloat16 *btpHi = nullptr, *btpLo = nullptr;
    __nv_bfloat16 *wtHi = nullptr, *wtLo = nullptr;
    cudaGetSymbolAddress((void**)&bufA, g_bufA);
    cudaGetSymbolAddress((void**)&bufB, g_bufB);
    cudaGetSymbolAddress((void**)&btgHi, g_btg_hi);
    cudaGetSymbolAddress((void**)&btgLo, g_btg_lo);
    cudaGetSymbolAddress((void**)&btpHi, g_btp_hi);
    cudaGetSymbolAddress((void**)&btpLo, g_btp_lo);
    cudaGetSymbolAddress((void**)&wtHi, g_wt_hi);
    cudaGetSymbolAddress((void**)&wtLo, g_wt_lo);

    __nv_bfloat16* gHi[2] = { btgHi, btgHi + (size_t)BB * FF * NN };
    __nv_bfloat16* gLo[2] = { btgLo, btgLo + (size_t)BB * FF * NN };

    cudaFuncSetAttribute(cheb_gemm_tc, cudaFuncAttributeMaxDynamicSharedMemorySize, SMEM_TOTAL);
    cudaFuncSetAttribute(proj_mma, cudaFuncAttributeMaxDynamicSharedMemorySize, PJ_SMEM);

    const dim3 gGrid(NN / BM, BB);
    const dim3 bGrid((BB * FF * NN) / 256);
    const dim3 wGrid((PK * OO) / 256);
    const dim3 pjGrid((BB * NN) / 64, 2);

    prep_w<<<wGrid, 256>>>(W, theta, wtHi, wtLo);
    prep_b<<<bGrid, 256>>>(x, gHi[0], gLo[0], btpHi, btpLo);

    // T1 = L @ x
    cheb_gemm_tc<<<gGrid, 128, SMEM_TOTAL>>>(Lm, gHi[0], gLo[0], x, bufA, 1.0f, 0.0f,
                                             gHi[1], gLo[1], btpHi, btpLo, 1);
    // T2 = 2 L @ T1 - x
    cheb_gemm_tc<<<gGrid, 128, SMEM_TOTAL>>>(Lm, gHi[1], gLo[1], x, bufB, 2.0f, -1.0f,
                                             gHi[0], gLo[0], btpHi, btpLo, 2);
    // T3 = 2 L @ T2 - T1
    cheb_gemm_tc<<<gGrid, 128, SMEM_TOTAL>>>(Lm, gHi[0], gLo[0], bufA, bufA, 2.0f, -1.0f,
                                             gHi[1], gLo[1], btpHi, btpLo, 3);
    // T4 = 2 L @ T3 - T2
    cheb_gemm_tc<<<gGrid, 128, SMEM_TOTAL>>>(Lm, gHi[1], gLo[1], bufB, bufB, 2.0f, -1.0f,
                                             gHi[0], gLo[0], btpHi, btpLo, 4);
    // T5 = 2 L @ T4 - T3
    cheb_gemm_tc<<<gGrid, 128, SMEM_TOTAL>>>(Lm, gHi[0], gLo[0], bufA, bufA, 2.0f, -1.0f,
                                             gHi[1], gLo[1], btpHi, btpLo, 5);

    // out = sum_k theta_k T_k W_k
    proj_mma<<<pjGrid, 256, PJ_SMEM>>>(btpHi, btpLo, wtHi, wtLo, out);
}

// round 16
// speedup vs baseline: 1.7712x; 1.0257x over previous
#include <cuda_runtime.h>
#include <cuda_bf16.h>
#include <cstdint>

#define BB 4
#define NN 4096
#define FF 32
#define KK 6
#define OO 128

// ---- GEMM tiling ----
#define BM 64                   // rows per CTA (4 warps x 16 rows)
#define KC 32                   // k per chunk
#define NSTAGE 6
#define NCHUNK (NN / KC)        // 128
#define PK (KK * FF)            // 192

#define AROWF 40                                // A smem row stride in floats
#define AROWB (AROWF * 4)
#define A_BYTES (BM * AROWB)                    // 10240
#define BROWB 80                                // B smem row stride bytes
#define B_BYTES (FF * BROWB)                    // 2560
#define BHI_OFF A_BYTES
#define BLO_OFF (A_BYTES + B_BYTES)
#define STAGE_BYTES (A_BYTES + 2 * B_BYTES)     // 15360
#define SMEM_TOTAL (NSTAGE * STAGE_BYTES)       // 92160

// ---- scratch ----
__device__ float g_bufA[BB * NN * FF];
__device__ float g_bufB[BB * NN * FF];
__device__ __nv_bfloat16 g_btg_hi[2][BB * FF * NN];
__device__ __nv_bfloat16 g_btg_lo[2][BB * FF * NN];
__device__ __nv_bfloat16 g_btp_hi[(size_t)BB * NN * PK];
__device__ __nv_bfloat16 g_btp_lo[(size_t)BB * NN * PK];
__device__ __nv_bfloat16 g_wt_hi[OO * PK];
__device__ __nv_bfloat16 g_wt_lo[OO * PK];

__device__ __forceinline__ uint32_t smem_u32(const void* p) {
    uint32_t a;
    asm("{ .reg .u64 t; cvta.to.shared.u64 t, %1; cvt.u32.u64 %0, t; }" : "=r"(a) : "l"(p));
    return a;
}
__device__ __forceinline__ void cp16(uint32_t dst, const void* src) {
    asm volatile("cp.async.cg.shared.global [%0], [%1], 16;" :: "r"(dst), "l"(src));
}
#define CP_COMMIT() asm volatile("cp.async.commit_group;" ::: "memory")
#define CP_WAIT(n)  asm volatile("cp.async.wait_group %0;" :: "n"(n) : "memory")

__device__ __forceinline__ void split2(float x, float y, uint32_t& hi, uint32_t& lo) {
    asm("cvt.rn.bf16x2.f32 %0, %1, %2;" : "=r"(hi) : "f"(y), "f"(x));
    const float h0 = __uint_as_float(hi << 16);
    const float h1 = __uint_as_float(hi & 0xFFFF0000u);
    const float l0 = x - h0;
    const float l1 = y - h1;
    asm("cvt.rn.bf16x2.f32 %0, %1, %2;" : "=r"(lo) : "f"(l1), "f"(l0));
}

__device__ __forceinline__ void mma16816(float* c,
                                         uint32_t a0, uint32_t a1, uint32_t a2, uint32_t a3,
                                         uint32_t b0, uint32_t b1) {
    asm volatile(
        "mma.sync.aligned.m16n8k16.row.col.f32.bf16.bf16.f32 "
        "{%0,%1,%2,%3}, {%4,%5,%6,%7}, {%8,%9}, {%0,%1,%2,%3};"
        : "+f"(c[0]), "+f"(c[1]), "+f"(c[2]), "+f"(c[3])
        : "r"(a0), "r"(a1), "r"(a2), "r"(a3), "r"(b0), "r"(b1));
}

// ---------------------------------------------------------------------------
// Prep x: fp32 [b][n][f] -> btg ([b][f][n] hi/lo)  +  btp slot 0
// ---------------------------------------------------------------------------
__global__ __launch_bounds__(256) void prep_b(
    const float* __restrict__ T,
    __nv_bfloat16* __restrict__ gHi,
    __nv_bfloat16* __restrict__ gLo,
    __nv_bfloat16* __restrict__ pHi,
    __nv_bfloat16* __restrict__ pLo)
{
    const int idx = blockIdx.x * 256 + threadIdx.x;
    const int n = idx & (NN - 1);
    const int f = (idx >> 12) & (FF - 1);
    const int b = idx >> 17;
    const float a = T[((size_t)b * NN + n) * FF + f];
    const __nv_bfloat16 h = __float2bfloat16_rn(a);
    const __nv_bfloat16 l = __float2bfloat16_rn(a - __bfloat162float(h));
    gHi[idx] = h;
    gLo[idx] = l;
    const size_t pidx = ((size_t)b * NN + n) * PK + f;
    pHi[pidx] = h;
    pLo[pidx] = l;
}

// ---------------------------------------------------------------------------
// Prep W': Wt[o][k6*32+f] = theta[k6] * W[k6][f][o], bf16 hi/lo
// ---------------------------------------------------------------------------
__global__ __launch_bounds__(256) void prep_w(
    const float* __restrict__ W,
    const float* __restrict__ theta,
    __nv_bfloat16* __restrict__ wHi,
    __nv_bfloat16* __restrict__ wLo)
{
    const int idx = blockIdx.x * 256 + threadIdx.x;
    const int o  = idx & (OO - 1);
    const int kf = idx >> 7;
    const int k6 = kf >> 5;
    const float v = theta[k6] * W[(size_t)kf * OO + o];
    const __nv_bfloat16 h = __float2bfloat16_rn(v);
    const size_t w = (size_t)o * PK + kf;
    wHi[w] = h;
    wLo[w] = __float2bfloat16_rn(v - __bfloat162float(h));
}

// ---------------------------------------------------------------------------
// HMMA GEMM: fine-grained interleaved cp.async (1 cp16/thread per slice, 6
// slices spread across the compute phase), 6-stage ring, unconditional commit.
// Tnew = alpha * L @ Tprev + beta * Tpp, plus bf16 term export.
// ---------------------------------------------------------------------------
__global__ __launch_bounds__(128, 2) void cheb_gemm_tc(
    const float* __restrict__ Lmat,
    const __nv_bfloat16* __restrict__ BtHi,
    const __nv_bfloat16* __restrict__ BtLo,
    const float* __restrict__ Tpp,
    float* __restrict__ Tnew,
    float alpha, float beta,
    __nv_bfloat16* __restrict__ outGHi,
    __nv_bfloat16* __restrict__ outGLo,
    __nv_bfloat16* __restrict__ outPHi,
    __nv_bfloat16* __restrict__ outPLo,
    int pslot)
{
    extern __shared__ __align__(16) char smem[];
    const uint32_t sb = smem_u32(smem);

    const int tid  = threadIdx.x;
    const int lane = tid & 31;
    const int wl   = tid >> 5;
    const int b    = blockIdx.y;
    const int row0 = blockIdx.x * BM;

    const float* Lb = Lmat + ((size_t)b * NN + row0) * NN;
    const __nv_bfloat16* bhsrc = BtHi + (size_t)b * FF * NN;
    const __nv_bfloat16* blsrc = BtLo + (size_t)b * FF * NN;

    // one slice = 1 cp16 per thread. u in 0..5: 0..3 = A quarters, 4 = B hi, 5 = B lo
    auto issueU = [&](int c, int u) {
        const uint32_t st = sb + (uint32_t)(c % NSTAGE) * STAGE_BYTES;
        const int k0 = c * KC;
        if (u < 4) {
            const int idx = u * 128 + tid;
            const int r = idx >> 3, g = idx & 7;
            cp16(st + r * AROWB + g * 16, Lb + (size_t)r * NN + k0 + g * 4);
        } else {
            const int f = tid >> 2, g = tid & 3;
            if (u == 4)
                cp16(st + BHI_OFF + f * BROWB + g * 16, bhsrc + (size_t)f * NN + k0 + g * 8);
            else
                cp16(st + BLO_OFF + f * BROWB + g * 16, blsrc + (size_t)f * NN + k0 + g * 8);
        }
    };

    // prologue: stages 0..NSTAGE-2
#pragma unroll
    for (int s = 0; s < NSTAGE - 1; s++) {
#pragma unroll
        for (int u = 0; u < 6; u++) issueU(s, u);
        CP_COMMIT();
    }

    float acc[4][4];
#pragma unroll
    for (int i = 0; i < 4; i++)
#pragma unroll
        for (int j = 0; j < 4; j++) acc[i][j] = 0.0f;

    const int rsub = (lane >> 2);
    const int kq   = (lane & 3) * 2;

    for (int i = 0; i < NCHUNK; i++) {
        CP_WAIT(NSTAGE - 2);
        __syncthreads();

        const bool pf = (i + NSTAGE - 1 < NCHUNK);
        const int  pc = i + NSTAGE - 1;
        const char* st = smem + (i % NSTAGE) * STAGE_BYTES;
        const float* As = (const float*)st;

#pragma unroll
        for (int kf = 0; kf < 2; kf++) {
            const int kb = kf * 16;
            const float* Ap = As + (wl * 16 + rsub) * AROWF + kb + kq;
            const float2 p0 = *(const float2*)(Ap);
            const float2 p1 = *(const float2*)(Ap + 8 * AROWF);
            const float2 p2 = *(const float2*)(Ap + 8);
            const float2 p3 = *(const float2*)(Ap + 8 * AROWF + 8);

            uint32_t ah0, ah1, ah2, ah3, al0, al1, al2, al3;
            split2(p0.x, p0.y, ah0, al0);
            split2(p1.x, p1.y, ah1, al1);
            split2(p2.x, p2.y, ah2, al2);
            split2(p3.x, p3.y, ah3, al3);

#pragma unroll
            for (int nb = 0; nb < 4; nb++) {
                const int n = nb * 8 + rsub;
                const char* bp = st + BHI_OFF + n * BROWB + (kb + kq) * 2;
                const uint32_t bh0 = *(const uint32_t*)(bp);
                const uint32_t bh1 = *(const uint32_t*)(bp + 16);
                const uint32_t bl0 = *(const uint32_t*)(bp + (BLO_OFF - BHI_OFF));
                const uint32_t bl1 = *(const uint32_t*)(bp + (BLO_OFF - BHI_OFF) + 16);

                mma16816(acc[nb], ah0, ah1, ah2, ah3, bh0, bh1);
                mma16816(acc[nb], ah0, ah1, ah2, ah3, bl0, bl1);
                mma16816(acc[nb], al0, al1, al2, al3, bh0, bh1);

                // fine-grained prefetch: 1 cp16/thread after nb 0,1,2
                if (pf && nb < 3) issueU(pc, kf * 3 + nb);
            }
        }
        CP_COMMIT();   // unconditional: empty tail groups keep wait-count aligned
    }

    // ---- epilogue: Tnew fp32 + btg [f][n] hi/lo + btp slab slot ----
    const int rA = row0 + wl * 16 + rsub;
#pragma unroll
    for (int nb = 0; nb < 4; nb++) {
        const int col = nb * 8 + kq;
        const size_t o0 = ((size_t)b * NN + rA) * FF + col;
        const size_t o1 = o0 + 8 * FF;
        float2 v0 = make_float2(alpha * acc[nb][0], alpha * acc[nb][1]);
        float2 v1 = make_float2(alpha * acc[nb][2], alpha * acc[nb][3]);
        if (beta != 0.0f) {
            const float2 q0 = *(const float2*)(Tpp + o0);
            const float2 q1 = *(const float2*)(Tpp + o1);
            v0.x += beta * q0.x; v0.y += beta * q0.y;
            v1.x += beta * q1.x; v1.y += beta * q1.y;
        }
        *(float2*)(Tnew + o0) = v0;
        *(float2*)(Tnew + o1) = v1;

        uint32_t h0, l0, h1, l1;
        split2(v0.x, v0.y, h0, l0);
        split2(v1.x, v1.y, h1, l1);

        const size_t p0 = ((size_t)b * NN + rA) * PK + pslot * FF + col;
        const size_t p1 = p0 + 8 * PK;
        *(uint32_t*)(outPHi + p0) = h0;
        *(uint32_t*)(outPLo + p0) = l0;
        *(uint32_t*)(outPHi + p1) = h1;
        *(uint32_t*)(outPLo + p1) = l1;

        const size_t gA = ((size_t)b * FF + col) * NN;
        ((uint16_t*)outGHi)[gA + rA]           = (uint16_t)(h0 & 0xFFFF);
        ((uint16_t*)outGHi)[gA + NN + rA]      = (uint16_t)(h0 >> 16);
        ((uint16_t*)outGLo)[gA + rA]           = (uint16_t)(l0 & 0xFFFF);
        ((uint16_t*)outGLo)[gA + NN + rA]      = (uint16_t)(l0 >> 16);
        ((uint16_t*)outGHi)[gA + rA + 8]       = (uint16_t)(h1 & 0xFFFF);
        ((uint16_t*)outGHi)[gA + NN + rA + 8]  = (uint16_t)(h1 >> 16);
        ((uint16_t*)outGLo)[gA + rA + 8]       = (uint16_t)(l1 & 0xFFFF);
        ((uint16_t*)outGLo)[gA + NN + rA + 8]  = (uint16_t)(l1 >> 16);
    }
}

// ---------------------------------------------------------------------------
// Fused projection: out[16384,128] = A[16384,192] @ W'[192,128]
// ---------------------------------------------------------------------------
#define PJ_STRIDE 100
#define PJ_SMEM (4 * 64 * PJ_STRIDE * 4)

__global__ __launch_bounds__(256, 2) void proj_mma(
    const __nv_bfloat16* __restrict__ pHi,
    const __nv_bfloat16* __restrict__ pLo,
    const __nv_bfloat16* __restrict__ wHi,
    const __nv_bfloat16* __restrict__ wLo,
    float* __restrict__ out)
{
    extern __shared__ __align__(16) char smem[];
    uint32_t* Ah = (uint32_t*)smem;
    uint32_t* Al = Ah + 64 * PJ_STRIDE;
    uint32_t* Bh = Al + 64 * PJ_STRIDE;
    uint32_t* Bl = Bh + 64 * PJ_STRIDE;
    const uint32_t sAh = smem_u32(Ah), sAl = smem_u32(Al);
    const uint32_t sBh = smem_u32(Bh), sBl = smem_u32(Bl);

    const int tid = threadIdx.x;
    const int r0 = blockIdx.x * 64;
    const int oh = blockIdx.y;

#pragma unroll
    for (int i = 0; i < 6; i++) {
        const int idx = i * 256 + tid;
        const int row = idx / 24;
        const int ch  = idx % 24;
        cp16(sAh + row * 400 + ch * 16, pHi + (size_t)(r0 + row) * PK + ch * 8);
        cp16(sAl + row * 400 + ch * 16, pLo + (size_t)(r0 + row) * PK + ch * 8);
        cp16(sBh + row * 400 + ch * 16, wHi + (size_t)(oh * 64 + row) * PK + ch * 8);
        cp16(sBl + row * 400 + ch * 16, wLo + (size_t)(oh * 64 + row) * PK + ch * 8);
    }
    CP_COMMIT();
    CP_WAIT(0);
    __syncthreads();

    const int lane = tid & 31;
    const int wid  = tid >> 5;
    const int mw   = wid & 3;
    const int ow   = wid >> 2;
    const int rsub = lane >> 2;
    const int q    = lane & 3;

    float acc[4][4];
#pragma unroll
    for (int i = 0; i < 4; i++)
#pragma unroll
        for (int j = 0; j < 4; j++) acc[i][j] = 0.0f;

#pragma unroll
    for (int ki = 0; ki < 12; ki++) {
        const int kb2 = ki * 8;
        const uint32_t* Ar = Ah + (mw * 16 + rsub) * PJ_STRIDE + kb2 + q;
        const uint32_t* Alr = Al + (mw * 16 + rsub) * PJ_STRIDE + kb2 + q;
        const uint32_t ah0 = Ar[0],  ah1 = Ar[8 * PJ_STRIDE],  ah2 = Ar[4],  ah3 = Ar[8 * PJ_STRIDE + 4];
        const uint32_t al0 = Alr[0], al1 = Alr[8 * PJ_STRIDE], al2 = Alr[4], al3 = Alr[8 * PJ_STRIDE + 4];

#pragma unroll
        for (int nb = 0; nb < 4; nb++) {
            const int ob = ow * 32 + nb * 8 + rsub;
            const uint32_t* Br = Bh + ob * PJ_STRIDE + kb2 + q;
            const uint32_t* Blr = Bl + ob * PJ_STRIDE + kb2 + q;
            const uint32_t bh0 = Br[0], bh1 = Br[4];
            const uint32_t bl0 = Blr[0], bl1 = Blr[4];

            mma16816(acc[nb], ah0, ah1, ah2, ah3, bh0, bh1);
            mma16816(acc[nb], ah0, ah1, ah2, ah3, bl0, bl1);
            mma16816(acc[nb], al0, al1, al2, al3, bh0, bh1);
        }
    }

    const int row = r0 + mw * 16 + rsub;
#pragma unroll
    for (int nb = 0; nb < 4; nb++) {
        const int col = oh * 64 + ow * 32 + nb * 8 + q * 2;
        *(float2*)(out + (size_t)row * OO + col)       = make_float2(acc[nb][0], acc[nb][1]);
        *(float2*)(out + (size_t)(row + 8) * OO + col) = make_float2(acc[nb][2], acc[nb][3]);
    }
}

// ---------------------------------------------------------------------------
// Launcher
// ---------------------------------------------------------------------------
extern "C" void kernel_launch(void* const* d_in, const int* in_sizes, int n_in,
                              void* d_out, int out_size)
{
    const float* x = nullptr;
    const float* Lm = nullptr;
    const float* W = nullptr;
    const float* theta = nullptr;
    for (int i = 0; i < n_in; i++) {
        switch (in_sizes[i]) {
            case BB * NN * FF: x = (const float*)d_in[i]; break;
            case BB * NN * NN: Lm = (const float*)d_in[i]; break;
            case KK * FF * OO: W = (const float*)d_in[i]; break;
            case KK:           theta = (const float*)d_in[i]; break;
            default: break;
        }
    }
    float* out = (float*)d_out;

    float *bufA = nullptr, *bufB = nullptr;
    __nv_bfloat16 *btgHi = nullptr, *btgLo = nullptr;
    __nv_bfloat16 *btpHi = nullptr, *btpLo = nullptr;
    __nv_bfloat16 *wtHi = nullptr, *wtLo = nullptr;
    cudaGetSymbolAddress((void**)&bufA, g_bufA);
    cudaGetSymbolAddress((void**)&bufB, g_bufB);
    cudaGetSymbolAddress((void**)&btgHi, g_btg_hi);
    cudaGetSymbolAddress((void**)&btgLo, g_btg_lo);
    cudaGetSymbolAddress((void**)&btpHi, g_btp_hi);
    cudaGetSymbolAddress((void**)&btpLo, g_btp_lo);
    cudaGetSymbolAddress((void**)&wtHi, g_wt_hi);
    cudaGetSymbolAddress((void**)&wtLo, g_wt_lo);

    __nv_bfloat16* gHi[2] = { btgHi, btgHi + (size_t)BB * FF * NN };
    __nv_bfloat16* gLo[2] = { btgLo, btgLo + (size_t)BB * FF * NN };

    cudaFuncSetAttribute(cheb_gemm_tc, cudaFuncAttributeMaxDynamicSharedMemorySize, SMEM_TOTAL);
    cudaFuncSetAttribute(proj_mma, cudaFuncAttributeMaxDynamicSharedMemorySize, PJ_SMEM);

    const dim3 gGrid(NN / BM, BB);
    const dim3 bGrid((BB * FF * NN) / 256);
    const dim3 wGrid((PK * OO) / 256);
    const dim3 pjGrid((BB * NN) / 64, 2);

    prep_w<<<wGrid, 256>>>(W, theta, wtHi, wtLo);
    prep_b<<<bGrid, 256>>>(x, gHi[0], gLo[0], btpHi, btpLo);

    // T1 = L @ x
    cheb_gemm_tc<<<gGrid, 128, SMEM_TOTAL>>>(Lm, gHi[0], gLo[0], x, bufA, 1.0f, 0.0f,
                                             gHi[1], gLo[1], btpHi, btpLo, 1);
    // T2 = 2 L @ T1 - x
    cheb_gemm_tc<<<gGrid, 128, SMEM_TOTAL>>>(Lm, gHi[1], gLo[1], x, bufB, 2.0f, -1.0f,
                                             gHi[0], gLo[0], btpHi, btpLo, 2);
    // T3 = 2 L @ T2 - T1
    cheb_gemm_tc<<<gGrid, 128, SMEM_TOTAL>>>(Lm, gHi[0], gLo[0], bufA, bufA, 2.0f, -1.0f,
                                             gHi[1], gLo[1], btpHi, btpLo, 3);
    // T4 = 2 L @ T3 - T2
    cheb_gemm_tc<<<gGrid, 128, SMEM_TOTAL>>>(Lm, gHi[1], gLo[1], bufB, bufB, 2.0f, -1.0f,
                                             gHi[0], gLo[0], btpHi, btpLo, 4);
    // T5 = 2 L @ T4 - T3
    cheb_gemm_tc<<<gGrid, 128, SMEM_TOTAL>>>(Lm, gHi[0], gLo[0], bufA, bufA, 2.0f, -1.0f,
                                             gHi[1], gLo[1], btpHi, btpLo, 5);

    // out = sum_k theta_k T_k W_k
    proj_mma<<<pjGrid, 256, PJ_SMEM>>>(btpHi, btpLo, wtHi, wtLo, out);
}